// round 2
// baseline (speedup 1.0000x reference)
#include <cuda_runtime.h>

// WaveletGatedNet: y = iwpt( threshold( wpt(x) * sigmoid(wpt(x) @ W^T + b) ) ) + x
// B=128, C=16, L=4096, LEVEL=3  ->  M = B*C*8 = 16384 rows of K=512 coeffs.
//
// Kernel 1 (wpt):  x -> g_coeffs  (3-stage Haar butterfly per 8-sample block)
// Kernel 2 (gemm): 128x128x16 fp32 SIMT GEMM (packed f32x2 FMA) with fused
//                  sigmoid/gate/threshold + cross-node inverse butterfly + x-add.

#define BM 128
#define BN 128
#define BK 16
#define TPB 256
#define M_TOTAL 16384
#define KDIM 512

__device__ float g_coeffs[M_TOTAL * KDIM];   // 32 MB scratch (allowed: __device__ global)

__device__ __forceinline__ unsigned long long pack2(float lo, float hi) {
    unsigned long long r;
    asm("mov.b64 %0, {%1, %2};" : "=l"(r) : "f"(lo), "f"(hi));
    return r;
}
__device__ __forceinline__ void fma2(unsigned long long& c, unsigned long long a,
                                     unsigned long long b) {
    asm("fma.rn.f32x2 %0, %1, %2, %0;" : "+l"(c) : "l"(a), "l"(b));
}
__device__ __forceinline__ float2 unpack2(unsigned long long v) {
    float2 f;
    asm("mov.b64 {%0, %1}, %2;" : "=f"(f.x), "=f"(f.y) : "l"(v));
    return f;
}

// ---------------------------------------------------------------------------
// Kernel 1: forward Haar wavelet packet (3 levels) on blocks of 8 samples.
// coeffs[(bc*8 + n)*512 + d] from x[bc*4096 + 8d .. 8d+7].
// ---------------------------------------------------------------------------
__global__ __launch_bounds__(256) void wpt_kernel(const float* __restrict__ x) {
    const float s = 0.70710678118654752440f;
    int t = blockIdx.x * blockDim.x + threadIdx.x;   // 0 .. 2048*512-1
    int bc = t >> 9;
    int d  = t & 511;

    const float4* xp = (const float4*)(x + (size_t)bc * 4096 + (size_t)d * 8);
    float4 v0 = xp[0];
    float4 v1 = xp[1];

    // level 1
    float a0 = (v0.x + v0.y) * s, d0 = (v0.x - v0.y) * s;
    float a1 = (v0.z + v0.w) * s, d1 = (v0.z - v0.w) * s;
    float a2 = (v1.x + v1.y) * s, d2 = (v1.x - v1.y) * s;
    float a3 = (v1.z + v1.w) * s, d3 = (v1.z - v1.w) * s;
    // level 2
    float aa0 = (a0 + a1) * s, da0 = (a0 - a1) * s;
    float aa1 = (a2 + a3) * s, da1 = (a2 - a3) * s;
    float ad0 = (d0 + d1) * s, dd0 = (d0 - d1) * s;
    float ad1 = (d2 + d3) * s, dd1 = (d2 - d3) * s;
    // level 3 (node order: children 2n, 2n+1)
    float c0 = (aa0 + aa1) * s, c1 = (aa0 - aa1) * s;
    float c2 = (da0 + da1) * s, c3 = (da0 - da1) * s;
    float c4 = (ad0 + ad1) * s, c5 = (ad0 - ad1) * s;
    float c6 = (dd0 + dd1) * s, c7 = (dd0 - dd1) * s;

    float* o = g_coeffs + (size_t)bc * 8 * 512 + d;
    o[0]        = c0;  o[512]      = c1;
    o[2 * 512]  = c2;  o[3 * 512]  = c3;
    o[4 * 512]  = c4;  o[5 * 512]  = c5;
    o[6 * 512]  = c6;  o[7 * 512]  = c7;
}

// ---------------------------------------------------------------------------
// Kernel 2: GEMM (logits = coeffs @ W^T) + fused gate/threshold/iwpt/add-x.
// Tile: BM=128 rows (16 complete (b,c) groups of 8 nodes) x BN=128 cols.
// ---------------------------------------------------------------------------
__global__ __launch_bounds__(TPB) void gemm_gate_iwpt(
        const float* __restrict__ W, const float* __restrict__ bias,
        const float* __restrict__ thrp, const float* __restrict__ x,
        float* __restrict__ out) {
    __shared__ float sm[8192];                 // 32 KB, aliased
    float* As = sm;                            // [BK][BM]
    float* Bs = sm + BK * BM;                  // [BK][BN]

    const int tid = threadIdx.x;
    const int rowTile = blockIdx.y * BM;
    const int colTile = blockIdx.x * BN;
    const int tx = tid & 15;
    const int ty = tid >> 4;
    const float* A = g_coeffs;

    unsigned long long acc[8][4];
#pragma unroll
    for (int i = 0; i < 8; i++)
#pragma unroll
        for (int j = 0; j < 4; j++) acc[i][j] = 0ull;   // (+0.f, +0.f)

    const int f0 = tid * 2;
    float4 pa[2], pb[2];

    auto loadTiles = [&](int k0) {
#pragma unroll
        for (int i = 0; i < 2; i++) {
            int f = f0 + i;
            int r = f >> 2, kq = f & 3;
            pa[i] = *(const float4*)(A + (size_t)(rowTile + r) * KDIM + k0 + kq * 4);
            pb[i] = *(const float4*)(W + (size_t)(colTile + r) * KDIM + k0 + kq * 4);
        }
    };
    auto storeTiles = [&]() {
#pragma unroll
        for (int i = 0; i < 2; i++) {
            int f = f0 + i;
            int r = f >> 2, kq = f & 3;
            As[(kq * 4 + 0) * BM + r] = pa[i].x;
            As[(kq * 4 + 1) * BM + r] = pa[i].y;
            As[(kq * 4 + 2) * BM + r] = pa[i].z;
            As[(kq * 4 + 3) * BM + r] = pa[i].w;
            Bs[(kq * 4 + 0) * BN + r] = pb[i].x;
            Bs[(kq * 4 + 1) * BN + r] = pb[i].y;
            Bs[(kq * 4 + 2) * BN + r] = pb[i].z;
            Bs[(kq * 4 + 3) * BN + r] = pb[i].w;
        }
    };

    loadTiles(0);
    storeTiles();
    __syncthreads();

    const int NKT = KDIM / BK;   // 32
    for (int kt = 0; kt < NKT; kt++) {
        if (kt + 1 < NKT) loadTiles((kt + 1) * BK);
#pragma unroll
        for (int k = 0; k < BK; k++) {
            float4 a0 = *(const float4*)&As[k * BM + ty * 4];
            float4 a1 = *(const float4*)&As[k * BM + 64 + ty * 4];
            float4 b0 = *(const float4*)&Bs[k * BN + tx * 4];
            float4 b1 = *(const float4*)&Bs[k * BN + 64 + tx * 4];
            unsigned long long bb[4] = {pack2(b0.x, b0.y), pack2(b0.z, b0.w),
                                        pack2(b1.x, b1.y), pack2(b1.z, b1.w)};
            float av[8] = {a0.x, a0.y, a0.z, a0.w, a1.x, a1.y, a1.z, a1.w};
#pragma unroll
            for (int i = 0; i < 8; i++) {
                unsigned long long aa = pack2(av[i], av[i]);
#pragma unroll
                for (int j = 0; j < 4; j++) fma2(acc[i][j], aa, bb[j]);
            }
        }
        __syncthreads();
        if (kt + 1 < NKT) {
            storeTiles();
            __syncthreads();
        }
    }

    // ---------------- epilogue: gate -> threshold -> iwpt -> +x ----------------
    const float thr = *thrp;
    const float s = 0.70710678118654752440f;
    float* sG = sm;               // reused as [64][BN] per half-pass (32 KB)
    const int bcBase = rowTile >> 3;

#pragma unroll
    for (int pass = 0; pass < 2; pass++) {
        __syncthreads();          // protect previous sG readers / mainloop smem
#pragma unroll
        for (int i = 0; i < 4; i++) {
            int ii = pass * 4 + i;                 // acc row index
            int rl = pass * 64 + ty * 4 + i;       // local row in 128-row tile
            int r  = rowTile + rl;
            const float* crow = A + (size_t)r * KDIM + colTile;
#pragma unroll
            for (int jh = 0; jh < 2; jh++) {
                int cl = jh * 64 + tx * 4;
                float4 cf = *(const float4*)(crow + cl);
                float cv[4] = {cf.x, cf.y, cf.z, cf.w};
#pragma unroll
                for (int q = 0; q < 4; q++) {
                    float2 p = unpack2(acc[ii][jh * 2 + (q >> 1)]);
                    float logit = ((q & 1) ? p.y : p.x) + bias[colTile + cl + q];
                    float gate = 1.0f / (1.0f + __expf(-logit));
                    float g = cv[q] * gate;
                    if (fabsf(g) < thr) g = 0.0f;
                    sG[(ty * 4 + i) * BN + cl + q] = g;
                }
            }
        }
        __syncthreads();

        // inverse butterfly over the 8 nodes of each (b,c) group in this half
        int e  = tid & 127;
        int gl = tid >> 7;     // 0..1
#pragma unroll
        for (int it = 0; it < 4; it++) {
            int gLoc = gl + it * 2;          // local group 0..7 within this pass
            int g    = pass * 8 + gLoc;      // tile group 0..15
            float gv[8];
#pragma unroll
            for (int n = 0; n < 8; n++) gv[n] = sG[(gLoc * 8 + n) * BN + e];

            // level-3 inverse
            float p0 = (gv[0] + gv[1]) * s, p1 = (gv[0] - gv[1]) * s;
            float p2 = (gv[2] + gv[3]) * s, p3 = (gv[2] - gv[3]) * s;
            float p4 = (gv[4] + gv[5]) * s, p5 = (gv[4] - gv[5]) * s;
            float p6 = (gv[6] + gv[7]) * s, p7 = (gv[6] - gv[7]) * s;
            // level-2 inverse
            float A0 = (p0 + p2) * s, A1 = (p0 - p2) * s;
            float A2 = (p1 + p3) * s, A3 = (p1 - p3) * s;
            float D0 = (p4 + p6) * s, D1 = (p4 - p6) * s;
            float D2 = (p5 + p7) * s, D3 = (p5 - p7) * s;
            // level-1 inverse
            float r0 = (A0 + D0) * s, r1 = (A0 - D0) * s;
            float r2 = (A1 + D1) * s, r3 = (A1 - D1) * s;
            float r4 = (A2 + D2) * s, r5 = (A2 - D2) * s;
            float r6 = (A3 + D3) * s, r7 = (A3 - D3) * s;

            size_t base = ((size_t)(bcBase + g)) * 4096 + (size_t)(colTile + e) * 8;
            float4 x0 = *(const float4*)(x + base);
            float4 x1 = *(const float4*)(x + base + 4);
            float4 o0 = make_float4(r0 + x0.x, r1 + x0.y, r2 + x0.z, r3 + x0.w);
            float4 o1 = make_float4(r4 + x1.x, r5 + x1.y, r6 + x1.z, r7 + x1.w);
            *(float4*)(out + base)     = o0;
            *(float4*)(out + base + 4) = o1;
        }
    }
}

// ---------------------------------------------------------------------------
extern "C" void kernel_launch(void* const* d_in, const int* in_sizes, int n_in,
                              void* d_out, int out_size) {
    const float* x   = (const float*)d_in[0];   // [128,16,4096]
    const float* W   = (const float*)d_in[1];   // [512,512]
    const float* b   = (const float*)d_in[2];   // [512]
    const float* thr = (const float*)d_in[3];   // scalar
    float* out = (float*)d_out;

    // 2048 (b,c) rows * 512 blocks-of-8 = 1,048,576 tasks
    wpt_kernel<<<4096, 256>>>(x);

    dim3 grid(KDIM / BN, M_TOTAL / BM);         // (4, 128)
    gemm_gate_iwpt<<<grid, TPB>>>(W, b, thr, x, out);
}

// round 5
// speedup vs baseline: 1.3846x; 1.3846x over previous
#include <cuda_runtime.h>
#include <cuda_bf16.h>
#include <cstdint>

// WaveletGatedNet (sm_100 plain target): bf16x3-split GEMM on mma.sync HMMA.
// logits = Ah*Wh + Al*Wh + Ah*Wl via single K=1536 bf16 GEMM,
// A' = [Ah | Al | (Ah re-read)],  B' = [Wh | Wh | Wl].

#define KD 512
#define KBIG 1536
#define BK 32
#define NKITER 48              // 1536 / 32
#define TPB 256
#define M_TOTAL 16384
#define ASTRIDE 40             // bf16 per smem row (32 data + 8 pad -> 80B stride)
#define STAGE_HALF (128 * ASTRIDE)            // bf16 elements per matrix per stage
#define STAGE_BYTES (2 * STAGE_HALF * 2)      // A + B, bytes  (20480)
#define EPI_BYTES (128 * 129 * 4 + 512)       // sG + bias
#define DSMEM_BYTES (3 * STAGE_BYTES > EPI_BYTES ? 3 * STAGE_BYTES : EPI_BYTES)

__device__ unsigned short g_A_u[(size_t)M_TOTAL * 1024]; // [16384][1024] = (Ah|Al)
__device__ unsigned short g_B_u[(size_t)KD * KBIG];      // [512][1536] = (Wh|Wh|Wl)

static __device__ __forceinline__ uint32_t smem_u32(const void* p) {
    uint32_t a;
    asm("{ .reg .u64 t; cvta.to.shared.u64 t, %1; cvt.u32.u64 %0, t; }"
        : "=r"(a) : "l"(p));
    return a;
}
static __device__ __forceinline__ void cp16(uint32_t dst, const void* src) {
    asm volatile("cp.async.cg.shared.global [%0], [%1], 16;"
                 :: "r"(dst), "l"(__cvta_generic_to_global(src)) : "memory");
}
static __device__ __forceinline__ void ldm_x4(uint32_t& r0, uint32_t& r1,
                                              uint32_t& r2, uint32_t& r3, uint32_t a) {
    asm volatile("ldmatrix.sync.aligned.m8n8.x4.shared.b16 {%0,%1,%2,%3}, [%4];"
                 : "=r"(r0), "=r"(r1), "=r"(r2), "=r"(r3) : "r"(a));
}
static __device__ __forceinline__ void mma16816(float* c, const uint32_t* a,
                                                uint32_t b0, uint32_t b1) {
    asm volatile("mma.sync.aligned.m16n8k16.row.col.f32.bf16.bf16.f32 "
                 "{%0,%1,%2,%3}, {%4,%5,%6,%7}, {%8,%9}, {%0,%1,%2,%3};"
                 : "+f"(c[0]), "+f"(c[1]), "+f"(c[2]), "+f"(c[3])
                 : "r"(a[0]), "r"(a[1]), "r"(a[2]), "r"(a[3]), "r"(b0), "r"(b1));
}

// ---------------------------------------------------------------------------
// Kernel 1: forward Haar WPT + bf16 hi/lo split.
// ---------------------------------------------------------------------------
__global__ __launch_bounds__(256) void wpt_split_kernel(const float* __restrict__ x) {
    const float s = 0.70710678118654752440f;
    int t = blockIdx.x * blockDim.x + threadIdx.x;
    int bc = t >> 9, d = t & 511;

    const float4* xp = (const float4*)(x + (size_t)bc * 4096 + (size_t)d * 8);
    float4 v0 = xp[0], v1 = xp[1];

    float a0 = (v0.x + v0.y) * s, d0 = (v0.x - v0.y) * s;
    float a1 = (v0.z + v0.w) * s, d1 = (v0.z - v0.w) * s;
    float a2 = (v1.x + v1.y) * s, d2 = (v1.x - v1.y) * s;
    float a3 = (v1.z + v1.w) * s, d3 = (v1.z - v1.w) * s;
    float aa0 = (a0 + a1) * s, da0 = (a0 - a1) * s;
    float aa1 = (a2 + a3) * s, da1 = (a2 - a3) * s;
    float ad0 = (d0 + d1) * s, dd0 = (d0 - d1) * s;
    float ad1 = (d2 + d3) * s, dd1 = (d2 - d3) * s;
    float cc[8];
    cc[0] = (aa0 + aa1) * s; cc[1] = (aa0 - aa1) * s;
    cc[2] = (da0 + da1) * s; cc[3] = (da0 - da1) * s;
    cc[4] = (ad0 + ad1) * s; cc[5] = (ad0 - ad1) * s;
    cc[6] = (dd0 + dd1) * s; cc[7] = (dd0 - dd1) * s;

    __nv_bfloat16* o = (__nv_bfloat16*)g_A_u + (size_t)(bc * 8) * 1024 + d;
#pragma unroll
    for (int n = 0; n < 8; ++n) {
        float v = cc[n];
        __nv_bfloat16 h = __float2bfloat16(v);
        float r = v - __bfloat162float(h);
        o[(size_t)n * 1024]       = h;
        o[(size_t)n * 1024 + 512] = __float2bfloat16(r);
    }
}

// ---------------------------------------------------------------------------
// Kernel 2: W -> (Wh | Wh | Wl)
// ---------------------------------------------------------------------------
__global__ __launch_bounds__(256) void wconv_kernel(const float* __restrict__ W) {
    int t = blockIdx.x * blockDim.x + threadIdx.x;
    int e = t >> 9, k = t & 511;
    float w = W[(size_t)e * 512 + k];
    __nv_bfloat16 h = __float2bfloat16(w);
    __nv_bfloat16 l = __float2bfloat16(w - __bfloat162float(h));
    __nv_bfloat16* o = (__nv_bfloat16*)g_B_u + (size_t)e * KBIG;
    o[k] = h; o[512 + k] = h; o[1024 + k] = l;
}

// ---------------------------------------------------------------------------
// Kernel 3: 128x128 CTA GEMM (HMMA) + fused gate/threshold/iwpt/add-x.
// ---------------------------------------------------------------------------
__global__ void __launch_bounds__(TPB) gemm_kernel(
        const float* __restrict__ bias, const float* __restrict__ thrp,
        const float* __restrict__ x, float* __restrict__ out) {
    extern __shared__ __align__(16) char dsm[];

    const int tid = threadIdx.x, wid = tid >> 5, lane = tid & 31;
    const int wm = wid & 1, wn = wid >> 1;          // 2 x 4 warp grid
    const int colTile = blockIdx.x * 128;           // fast dim: share A in L2
    const int rowTile = blockIdx.y * 128;
    const __nv_bfloat16* gA = (const __nv_bfloat16*)g_A_u;
    const __nv_bfloat16* gB = (const __nv_bfloat16*)g_B_u;
    const uint32_t sbase = smem_u32(dsm);

    float acc[4][4][4];
#pragma unroll
    for (int i = 0; i < 4; ++i)
#pragma unroll
        for (int j = 0; j < 4; ++j)
#pragma unroll
            for (int q = 0; q < 4; ++q) acc[i][j][q] = 0.f;

    auto load_stage = [&](int c, int st) {
        const int kbase = c * BK;
        const int aphys = (kbase < 1024) ? kbase : (kbase - 1024);
        uint32_t sA = sbase + st * STAGE_BYTES;
        uint32_t sB = sA + STAGE_HALF * 2;
#pragma unroll
        for (int p = 0; p < 4; ++p) {
            int q = tid + p * TPB;                  // 0..1023
            int mat = q >> 9, r = (q >> 2) & 127, ch = q & 3;
            if (mat == 0)
                cp16(sA + (r * ASTRIDE + ch * 8) * 2,
                     gA + (size_t)(rowTile + r) * 1024 + aphys + ch * 8);
            else
                cp16(sB + (r * ASTRIDE + ch * 8) * 2,
                     gB + (size_t)(colTile + r) * KBIG + kbase + ch * 8);
        }
        asm volatile("cp.async.commit_group;" ::: "memory");
    };

    load_stage(0, 0);
    load_stage(1, 1);

    // per-lane ldmatrix offsets (element units within a stage matrix)
    const int lrow = lane & 15;
    const int lcol = (lane >> 4) << 3;

    for (int c = 0; c < NKITER; ++c) {
        int st = c % 3;
        asm volatile("cp.async.wait_group 1;" ::: "memory");
        __syncthreads();

        uint32_t sA = sbase + st * STAGE_BYTES;
        uint32_t sB = sA + STAGE_HALF * 2;
#pragma unroll
        for (int kk = 0; kk < 2; ++kk) {
            const int k0 = kk * 16;
            uint32_t af[4][4];
#pragma unroll
            for (int mt = 0; mt < 4; ++mt) {
                int row = wm * 64 + mt * 16 + lrow;
                ldm_x4(af[mt][0], af[mt][1], af[mt][2], af[mt][3],
                       sA + (row * ASTRIDE + k0 + lcol) * 2);
            }
            uint32_t bf[2][4];
#pragma unroll
            for (int nn = 0; nn < 2; ++nn) {
                int row = wn * 32 + nn * 16 + lrow;
                ldm_x4(bf[nn][0], bf[nn][1], bf[nn][2], bf[nn][3],
                       sB + (row * ASTRIDE + k0 + lcol) * 2);
            }
#pragma unroll
            for (int mt = 0; mt < 4; ++mt)
#pragma unroll
                for (int nt = 0; nt < 4; ++nt) {
                    int nn = nt >> 1, hi = nt & 1;
                    mma16816(acc[mt][nt], af[mt], bf[nn][hi], bf[nn][2 + hi]);
                }
        }
        __syncthreads();
        if (c + 2 < NKITER) load_stage(c + 2, (c + 2) % 3);
    }
    asm volatile("cp.async.wait_group 0;" ::: "memory");
    __syncthreads();

    // ---------------- epilogue ----------------
    float* sG    = (float*)dsm;                     // [128][129]
    float* sBias = (float*)(dsm + 128 * 129 * 4);
    for (int i = tid; i < 128; i += TPB) sBias[i] = bias[colTile + i];
    __syncthreads();

    const float thr = thrp[0];
    const int rq = lane >> 2, cq = (lane & 3) * 2;

#pragma unroll
    for (int mt = 0; mt < 4; ++mt)
#pragma unroll
        for (int nt = 0; nt < 4; ++nt)
#pragma unroll
            for (int h = 0; h < 2; ++h) {
                int row = wm * 64 + mt * 16 + rq + h * 8;
                int col = wn * 32 + nt * 8 + cq;
                // coeff pair (bf16x2 hi and lo) at (rowTile+row, colTile+col)
                uint32_t ph = *(const uint32_t*)(gA + (size_t)(rowTile + row) * 1024 +
                                                 colTile + col);
                uint32_t pl = *(const uint32_t*)(gA + (size_t)(rowTile + row) * 1024 +
                                                 512 + colTile + col);
                __nv_bfloat162 hh = *(__nv_bfloat162*)&ph;
                __nv_bfloat162 ll = *(__nv_bfloat162*)&pl;
                float co0 = __bfloat162float(hh.x) + __bfloat162float(ll.x);
                float co1 = __bfloat162float(hh.y) + __bfloat162float(ll.y);
                float l0 = acc[mt][nt][h * 2 + 0] + sBias[col];
                float l1 = acc[mt][nt][h * 2 + 1] + sBias[col + 1];
                float g0 = co0 / (1.0f + __expf(-l0));
                float g1 = co1 / (1.0f + __expf(-l1));
                if (fabsf(g0) < thr) g0 = 0.0f;
                if (fabsf(g1) < thr) g1 = 0.0f;
                sG[row * 129 + col]     = g0;
                sG[row * 129 + col + 1] = g1;
            }
    __syncthreads();

    const float s2 = 0.70710678118654752440f;
    const int bcBase = rowTile >> 3;
#pragma unroll
    for (int p = 0; p < 8; ++p) {
        int t = tid + p * TPB;           // 0..2047
        int gl = t >> 7, d = t & 127;
        float gv[8];
#pragma unroll
        for (int n = 0; n < 8; ++n) gv[n] = sG[(gl * 8 + n) * 129 + d];

        float p0 = (gv[0] + gv[1]) * s2, p1 = (gv[0] - gv[1]) * s2;
        float p2 = (gv[2] + gv[3]) * s2, p3 = (gv[2] - gv[3]) * s2;
        float p4 = (gv[4] + gv[5]) * s2, p5 = (gv[4] - gv[5]) * s2;
        float p6 = (gv[6] + gv[7]) * s2, p7 = (gv[6] - gv[7]) * s2;
        float A0 = (p0 + p2) * s2, A1 = (p0 - p2) * s2;
        float A2 = (p1 + p3) * s2, A3 = (p1 - p3) * s2;
        float D0 = (p4 + p6) * s2, D1 = (p4 - p6) * s2;
        float D2 = (p5 + p7) * s2, D3 = (p5 - p7) * s2;
        float r0 = (A0 + D0) * s2, r1 = (A0 - D0) * s2;
        float r2 = (A1 + D1) * s2, r3 = (A1 - D1) * s2;
        float r4 = (A2 + D2) * s2, r5 = (A2 - D2) * s2;
        float r6 = (A3 + D3) * s2, r7 = (A3 - D3) * s2;

        size_t off = (size_t)(bcBase + gl) * 4096 + (size_t)(colTile + d) * 8;
        float4 x0 = *(const float4*)(x + off);
        float4 x1 = *(const float4*)(x + off + 4);
        *(float4*)(out + off)     = make_float4(r0 + x0.x, r1 + x0.y, r2 + x0.z, r3 + x0.w);
        *(float4*)(out + off + 4) = make_float4(r4 + x1.x, r5 + x1.y, r6 + x1.z, r7 + x1.w);
    }
}

// ---------------------------------------------------------------------------
extern "C" void kernel_launch(void* const* d_in, const int* in_sizes, int n_in,
                              void* d_out, int out_size) {
    const float* x   = (const float*)d_in[0];
    const float* W   = (const float*)d_in[1];
    const float* b   = (const float*)d_in[2];
    const float* thr = (const float*)d_in[3];
    float* out = (float*)d_out;

    cudaFuncSetAttribute(gemm_kernel, cudaFuncAttributeMaxDynamicSharedMemorySize,
                         DSMEM_BYTES);

    wpt_split_kernel<<<4096, 256>>>(x);
    wconv_kernel<<<1024, 256>>>(W);
    dim3 grid(KD / 128, M_TOTAL / 128);   // (4, 128), col fast for L2 A-sharing
    gemm_kernel<<<grid, TPB, DSMEM_BYTES>>>(b, thr, x, out);
}

// round 6
// speedup vs baseline: 1.5698x; 1.1338x over previous
#include <cuda_runtime.h>
#include <cuda_bf16.h>
#include <cstdint>

// WaveletGatedNet (sm_100 plain target): bf16x3-split GEMM on mma.sync HMMA.
// logits = Ah*Wh + Al*Wh + Ah*Wl via single K=1536 bf16 GEMM.
// R6: BK=64, 3-stage cp.async pipeline, ONE barrier per k-iter.

#define KD 512
#define KBIG 1536
#define BK 64
#define NKITER 24              // 1536 / 64
#define TPB 256
#define M_TOTAL 16384
#define ASTRIDE 72             // bf16 per smem row (64 data + 8 pad -> 144B stride)
#define STAGE_HALF (128 * ASTRIDE)            // bf16 elems per matrix per stage
#define STAGE_BYTES (2 * STAGE_HALF * 2)      // A + B bytes (36864)
#define EPI_BYTES (128 * 129 * 4 + 512)       // sG + bias (66560)
#define DSMEM_BYTES (3 * STAGE_BYTES)         // 110592 > EPI_BYTES

__device__ unsigned short g_A_u[(size_t)M_TOTAL * 1024]; // [16384][1024] = (Ah|Al)
__device__ unsigned short g_B_u[(size_t)KD * KBIG];      // [512][1536] = (Wh|Wh|Wl)

static __device__ __forceinline__ uint32_t smem_u32(const void* p) {
    uint32_t a;
    asm("{ .reg .u64 t; cvta.to.shared.u64 t, %1; cvt.u32.u64 %0, t; }"
        : "=r"(a) : "l"(p));
    return a;
}
static __device__ __forceinline__ void cp16(uint32_t dst, const void* src) {
    asm volatile("cp.async.cg.shared.global [%0], [%1], 16;"
                 :: "r"(dst), "l"(__cvta_generic_to_global(src)) : "memory");
}
static __device__ __forceinline__ void ldm_x4(uint32_t& r0, uint32_t& r1,
                                              uint32_t& r2, uint32_t& r3, uint32_t a) {
    asm volatile("ldmatrix.sync.aligned.m8n8.x4.shared.b16 {%0,%1,%2,%3}, [%4];"
                 : "=r"(r0), "=r"(r1), "=r"(r2), "=r"(r3) : "r"(a));
}
static __device__ __forceinline__ void mma16816(float* c, const uint32_t* a,
                                                uint32_t b0, uint32_t b1) {
    asm volatile("mma.sync.aligned.m16n8k16.row.col.f32.bf16.bf16.f32 "
                 "{%0,%1,%2,%3}, {%4,%5,%6,%7}, {%8,%9}, {%0,%1,%2,%3};"
                 : "+f"(c[0]), "+f"(c[1]), "+f"(c[2]), "+f"(c[3])
                 : "r"(a[0]), "r"(a[1]), "r"(a[2]), "r"(a[3]), "r"(b0), "r"(b1));
}

// ---------------------------------------------------------------------------
// Kernel 1: forward Haar WPT + bf16 hi/lo split.
// ---------------------------------------------------------------------------
__global__ __launch_bounds__(256) void wpt_split_kernel(const float* __restrict__ x) {
    const float s = 0.70710678118654752440f;
    int t = blockIdx.x * blockDim.x + threadIdx.x;
    int bc = t >> 9, d = t & 511;

    const float4* xp = (const float4*)(x + (size_t)bc * 4096 + (size_t)d * 8);
    float4 v0 = xp[0], v1 = xp[1];

    float a0 = (v0.x + v0.y) * s, d0 = (v0.x - v0.y) * s;
    float a1 = (v0.z + v0.w) * s, d1 = (v0.z - v0.w) * s;
    float a2 = (v1.x + v1.y) * s, d2 = (v1.x - v1.y) * s;
    float a3 = (v1.z + v1.w) * s, d3 = (v1.z - v1.w) * s;
    float aa0 = (a0 + a1) * s, da0 = (a0 - a1) * s;
    float aa1 = (a2 + a3) * s, da1 = (a2 - a3) * s;
    float ad0 = (d0 + d1) * s, dd0 = (d0 - d1) * s;
    float ad1 = (d2 + d3) * s, dd1 = (d2 - d3) * s;
    float cc[8];
    cc[0] = (aa0 + aa1) * s; cc[1] = (aa0 - aa1) * s;
    cc[2] = (da0 + da1) * s; cc[3] = (da0 - da1) * s;
    cc[4] = (ad0 + ad1) * s; cc[5] = (ad0 - ad1) * s;
    cc[6] = (dd0 + dd1) * s; cc[7] = (dd0 - dd1) * s;

    __nv_bfloat16* o = (__nv_bfloat16*)g_A_u + (size_t)(bc * 8) * 1024 + d;
#pragma unroll
    for (int n = 0; n < 8; ++n) {
        float v = cc[n];
        __nv_bfloat16 h = __float2bfloat16(v);
        float r = v - __bfloat162float(h);
        o[(size_t)n * 1024]       = h;
        o[(size_t)n * 1024 + 512] = __float2bfloat16(r);
    }
}

// ---------------------------------------------------------------------------
// Kernel 2: W -> (Wh | Wh | Wl)
// ---------------------------------------------------------------------------
__global__ __launch_bounds__(256) void wconv_kernel(const float* __restrict__ W) {
    int t = blockIdx.x * blockDim.x + threadIdx.x;
    int e = t >> 9, k = t & 511;
    float w = W[(size_t)e * 512 + k];
    __nv_bfloat16 h = __float2bfloat16(w);
    __nv_bfloat16 l = __float2bfloat16(w - __bfloat162float(h));
    __nv_bfloat16* o = (__nv_bfloat16*)g_B_u + (size_t)e * KBIG;
    o[k] = h; o[512 + k] = h; o[1024 + k] = l;
}

// ---------------------------------------------------------------------------
// Kernel 3: 128x128 CTA GEMM (HMMA) + fused gate/threshold/iwpt/add-x.
// ---------------------------------------------------------------------------
__global__ void __launch_bounds__(TPB) gemm_kernel(
        const float* __restrict__ bias, const float* __restrict__ thrp,
        const float* __restrict__ x, float* __restrict__ out) {
    extern __shared__ __align__(16) char dsm[];

    const int tid = threadIdx.x, wid = tid >> 5, lane = tid & 31;
    const int wm = wid & 1, wn = wid >> 1;          // 2 x 4 warp grid
    const int colTile = blockIdx.x * 128;           // fast dim: share A in L2
    const int rowTile = blockIdx.y * 128;
    const __nv_bfloat16* gA = (const __nv_bfloat16*)g_A_u;
    const __nv_bfloat16* gB = (const __nv_bfloat16*)g_B_u;
    const uint32_t sbase = smem_u32(dsm);

    float acc[4][4][4];
#pragma unroll
    for (int i = 0; i < 4; ++i)
#pragma unroll
        for (int j = 0; j < 4; ++j)
#pragma unroll
            for (int q = 0; q < 4; ++q) acc[i][j][q] = 0.f;

    auto load_stage = [&](int c, int st) {
        const int kbase = c * BK;
        const int aphys = (kbase < 1024) ? kbase : (kbase - 1024);
        uint32_t sA = sbase + st * STAGE_BYTES;
        uint32_t sB = sA + STAGE_HALF * 2;
#pragma unroll
        for (int p = 0; p < 8; ++p) {
            int q = tid + p * TPB;                  // 0..2047
            int mat = q >> 10, idx = q & 1023;
            int r = idx >> 3, ch = idx & 7;
            if (mat == 0)
                cp16(sA + (r * ASTRIDE + ch * 8) * 2,
                     gA + (size_t)(rowTile + r) * 1024 + aphys + ch * 8);
            else
                cp16(sB + (r * ASTRIDE + ch * 8) * 2,
                     gB + (size_t)(colTile + r) * KBIG + kbase + ch * 8);
        }
        asm volatile("cp.async.commit_group;" ::: "memory");
    };

    load_stage(0, 0);
    load_stage(1, 1);

    const int lrow = lane & 15;
    const int lcol = (lane >> 4) << 3;

    for (int c = 0; c < NKITER; ++c) {
        int st = c % 3;
        if (c < NKITER - 1)
            asm volatile("cp.async.wait_group 1;" ::: "memory");
        else
            asm volatile("cp.async.wait_group 0;" ::: "memory");
        __syncthreads();                            // single barrier per iter
        if (c + 2 < NKITER) load_stage(c + 2, (c + 2) % 3);

        uint32_t sA = sbase + st * STAGE_BYTES;
        uint32_t sB = sA + STAGE_HALF * 2;
#pragma unroll
        for (int kk = 0; kk < 4; ++kk) {
            const int k0 = kk * 16;
            uint32_t af[4][4];
#pragma unroll
            for (int mt = 0; mt < 4; ++mt) {
                int row = wm * 64 + mt * 16 + lrow;
                ldm_x4(af[mt][0], af[mt][1], af[mt][2], af[mt][3],
                       sA + (row * ASTRIDE + k0 + lcol) * 2);
            }
            uint32_t bf[2][4];
#pragma unroll
            for (int nn = 0; nn < 2; ++nn) {
                int row = wn * 32 + nn * 16 + lrow;
                ldm_x4(bf[nn][0], bf[nn][1], bf[nn][2], bf[nn][3],
                       sB + (row * ASTRIDE + k0 + lcol) * 2);
            }
#pragma unroll
            for (int mt = 0; mt < 4; ++mt)
#pragma unroll
                for (int nt = 0; nt < 4; ++nt) {
                    int nn = nt >> 1, hi = nt & 1;
                    mma16816(acc[mt][nt], af[mt], bf[nn][hi], bf[nn][2 + hi]);
                }
        }
    }
    __syncthreads();

    // ---------------- epilogue ----------------
    float* sG    = (float*)dsm;                     // [128][129]
    float* sBias = (float*)(dsm + 128 * 129 * 4);
    for (int i = tid; i < 128; i += TPB) sBias[i] = bias[colTile + i];
    __syncthreads();

    const float thr = thrp[0];
    const int rq = lane >> 2, cq = (lane & 3) * 2;

#pragma unroll
    for (int mt = 0; mt < 4; ++mt)
#pragma unroll
        for (int nt = 0; nt < 4; ++nt)
#pragma unroll
            for (int h = 0; h < 2; ++h) {
                int row = wm * 64 + mt * 16 + rq + h * 8;
                int col = wn * 32 + nt * 8 + cq;
                uint32_t ph = *(const uint32_t*)(gA + (size_t)(rowTile + row) * 1024 +
                                                 colTile + col);
                uint32_t pl = *(const uint32_t*)(gA + (size_t)(rowTile + row) * 1024 +
                                                 512 + colTile + col);
                __nv_bfloat162 hh = *(__nv_bfloat162*)&ph;
                __nv_bfloat162 ll = *(__nv_bfloat162*)&pl;
                float co0 = __bfloat162float(hh.x) + __bfloat162float(ll.x);
                float co1 = __bfloat162float(hh.y) + __bfloat162float(ll.y);
                float l0 = acc[mt][nt][h * 2 + 0] + sBias[col];
                float l1 = acc[mt][nt][h * 2 + 1] + sBias[col + 1];
                float g0 = co0 / (1.0f + __expf(-l0));
                float g1 = co1 / (1.0f + __expf(-l1));
                if (fabsf(g0) < thr) g0 = 0.0f;
                if (fabsf(g1) < thr) g1 = 0.0f;
                sG[row * 129 + col]     = g0;
                sG[row * 129 + col + 1] = g1;
            }
    __syncthreads();

    const float s2 = 0.70710678118654752440f;
    const int bcBase = rowTile >> 3;
#pragma unroll
    for (int p = 0; p < 8; ++p) {
        int t = tid + p * TPB;           // 0..2047
        int gl = t >> 7, d = t & 127;
        float gv[8];
#pragma unroll
        for (int n = 0; n < 8; ++n) gv[n] = sG[(gl * 8 + n) * 129 + d];

        float p0 = (gv[0] + gv[1]) * s2, p1 = (gv[0] - gv[1]) * s2;
        float p2 = (gv[2] + gv[3]) * s2, p3 = (gv[2] - gv[3]) * s2;
        float p4 = (gv[4] + gv[5]) * s2, p5 = (gv[4] - gv[5]) * s2;
        float p6 = (gv[6] + gv[7]) * s2, p7 = (gv[6] - gv[7]) * s2;
        float A0 = (p0 + p2) * s2, A1 = (p0 - p2) * s2;
        float A2 = (p1 + p3) * s2, A3 = (p1 - p3) * s2;
        float D0 = (p4 + p6) * s2, D1 = (p4 - p6) * s2;
        float D2 = (p5 + p7) * s2, D3 = (p5 - p7) * s2;
        float r0 = (A0 + D0) * s2, r1 = (A0 - D0) * s2;
        float r2 = (A1 + D1) * s2, r3 = (A1 - D1) * s2;
        float r4 = (A2 + D2) * s2, r5 = (A2 - D2) * s2;
        float r6 = (A3 + D3) * s2, r7 = (A3 - D3) * s2;

        size_t off = (size_t)(bcBase + gl) * 4096 + (size_t)(colTile + d) * 8;
        float4 x0 = *(const float4*)(x + off);
        float4 x1 = *(const float4*)(x + off + 4);
        *(float4*)(out + off)     = make_float4(r0 + x0.x, r1 + x0.y, r2 + x0.z, r3 + x0.w);
        *(float4*)(out + off + 4) = make_float4(r4 + x1.x, r5 + x1.y, r6 + x1.z, r7 + x1.w);
    }
}

// ---------------------------------------------------------------------------
extern "C" void kernel_launch(void* const* d_in, const int* in_sizes, int n_in,
                              void* d_out, int out_size) {
    const float* x   = (const float*)d_in[0];
    const float* W   = (const float*)d_in[1];
    const float* b   = (const float*)d_in[2];
    const float* thr = (const float*)d_in[3];
    float* out = (float*)d_out;

    cudaFuncSetAttribute(gemm_kernel, cudaFuncAttributeMaxDynamicSharedMemorySize,
                         DSMEM_BYTES);

    wpt_split_kernel<<<4096, 256>>>(x);
    wconv_kernel<<<1024, 256>>>(W);
    dim3 grid(KD / 128, M_TOTAL / 128);   // (4, 128), col fast for L2 A-sharing
    gemm_kernel<<<grid, TPB, DSMEM_BYTES>>>(b, thr, x, out);
}